// round 1
// baseline (speedup 1.0000x reference)
#include <cuda_runtime.h>
#include <cstdint>
#include <cfloat>

// Problem constants
#define NTOK 4096      // B*S = 2*2048
#define DMODEL 768
#define MDB 32768
#define KSEL 16
#define NHEAD 12
#define HDIM 64
#define DFF 3072

// ---------------- scratch (device globals; no allocations allowed) ----------
__device__ float g_h1[NTOK * DMODEL];                 // ln1 output
__device__ float g_q[NTOK * DMODEL];                  // q projection
__device__ float g_scores[(size_t)NTOK * MDB];        // knn scores (512MB)
__device__ int   g_idx[NTOK * KSEL];                  // top-k indices
__device__ float g_attn[NTOK * DMODEL];               // merged-head attention out
__device__ float g_res2[NTOK * DMODEL];               // residual2
__device__ float g_h2[NTOK * DMODEL];                 // ln2 output
__device__ float g_ff[NTOK * DFF];                    // mlp hidden

// ---------------- helpers ----------------------------------------------------
__device__ __forceinline__ float gelu_new(float x) {
    float x3 = x * x * x;
    float u = 0.7978845608028654f * (x + 0.044715f * x3);
    return 0.5f * x * (1.0f + tanhf(u));
}

// ---------------- layernorm ---------------------------------------------------
// one block (256 thr) per row of 768
__global__ void ln_kernel(const float* __restrict__ x,
                          const float* __restrict__ g,
                          const float* __restrict__ b,
                          float* __restrict__ out) {
    int row = blockIdx.x;
    int t = threadIdx.x;
    const float* xr = x + (size_t)row * DMODEL;
    float v[3];
#pragma unroll
    for (int i = 0; i < 3; i++) v[i] = xr[t + i * 256];
    float s = 0.f, s2 = 0.f;
#pragma unroll
    for (int i = 0; i < 3; i++) { s += v[i]; s2 += v[i] * v[i]; }
#pragma unroll
    for (int o = 16; o; o >>= 1) {
        s  += __shfl_down_sync(0xffffffffu, s, o);
        s2 += __shfl_down_sync(0xffffffffu, s2, o);
    }
    __shared__ float ws[8], ws2[8];
    int w = t >> 5, l = t & 31;
    if (l == 0) { ws[w] = s; ws2[w] = s2; }
    __syncthreads();
    if (t == 0) {
        float a = 0.f, a2 = 0.f;
#pragma unroll
        for (int i = 0; i < 8; i++) { a += ws[i]; a2 += ws2[i]; }
        float mu = a / DMODEL;
        ws[0] = mu;
        ws2[0] = a2 / DMODEL - mu * mu;
    }
    __syncthreads();
    float mu = ws[0];
    float rstd = rsqrtf(ws2[0] + 1e-5f);
    float* orow = out + (size_t)row * DMODEL;
#pragma unroll
    for (int i = 0; i < 3; i++) {
        int c = t + i * 256;
        orow[c] = (v[i] - mu) * rstd * g[c] + b[c];
    }
}

// ---------------- generic fp32 SIMT GEMM -------------------------------------
// C[m, n] (m over rows of A, n over Ncols) = A[m, :Kd] (lda=Kd) x B (+ epilogue)
// TRANSB=false: B is [Kd, ldb] row-major, use cols n0..n0+63
// TRANSB=true : B is [Ncols, ldb=Kd] row-major; C = A * B^T
// EPI: 0 none, 1 +bias, 2 +bias then gelu, 3 +bias +res
// Requires: M%64==0, Ncols%64==0, Kd%16==0 (all shapes here satisfy this)
template <bool TRANSB, int EPI>
__global__ void gemm_kernel(const float* __restrict__ A,
                            const float* __restrict__ B,
                            const float* __restrict__ bias,
                            const float* __restrict__ res,
                            float* __restrict__ C,
                            int Kd, int ldb, int Ncols) {
    __shared__ float As[16][64];
    __shared__ float Bs[16][64];
    int tid = threadIdx.x;
    int tx = tid & 15, ty = tid >> 4;
    int m0 = blockIdx.y * 64, n0 = blockIdx.x * 64;

    float acc[4][4] = {};

    int ar = tid >> 2;          // 0..63
    int ac4 = (tid & 3) * 4;    // 0,4,8,12
    const float* Aptr = A + (size_t)(m0 + ar) * Kd + ac4;
    const float* Bptr;
    int br = tid >> 4;          // 0..15  (non-trans path)
    int bc4 = (tid & 15) * 4;   // 0..60
    if (TRANSB) Bptr = B + (size_t)(n0 + ar) * ldb + ac4;
    else        Bptr = B + (size_t)br * ldb + n0 + bc4;

    for (int k0 = 0; k0 < Kd; k0 += 16) {
        float4 av = *(const float4*)(Aptr + k0);
        float4 bv;
        if (TRANSB) bv = *(const float4*)(Bptr + k0);
        else        bv = *(const float4*)(Bptr + (size_t)k0 * ldb);
        __syncthreads();
        As[ac4 + 0][ar] = av.x; As[ac4 + 1][ar] = av.y;
        As[ac4 + 2][ar] = av.z; As[ac4 + 3][ar] = av.w;
        if (TRANSB) {
            Bs[ac4 + 0][ar] = bv.x; Bs[ac4 + 1][ar] = bv.y;
            Bs[ac4 + 2][ar] = bv.z; Bs[ac4 + 3][ar] = bv.w;
        } else {
            *(float4*)&Bs[br][bc4] = bv;
        }
        __syncthreads();
#pragma unroll
        for (int k = 0; k < 16; k++) {
            float4 a = *(const float4*)&As[k][ty * 4];
            float4 b = *(const float4*)&Bs[k][tx * 4];
            acc[0][0] += a.x * b.x; acc[0][1] += a.x * b.y; acc[0][2] += a.x * b.z; acc[0][3] += a.x * b.w;
            acc[1][0] += a.y * b.x; acc[1][1] += a.y * b.y; acc[1][2] += a.y * b.z; acc[1][3] += a.y * b.w;
            acc[2][0] += a.z * b.x; acc[2][1] += a.z * b.y; acc[2][2] += a.z * b.z; acc[2][3] += a.z * b.w;
            acc[3][0] += a.w * b.x; acc[3][1] += a.w * b.y; acc[3][2] += a.w * b.z; acc[3][3] += a.w * b.w;
        }
    }

#pragma unroll
    for (int i = 0; i < 4; i++) {
        int row = m0 + ty * 4 + i;
        size_t base = (size_t)row * Ncols;
#pragma unroll
        for (int j = 0; j < 4; j++) {
            int col = n0 + tx * 4 + j;
            float v = acc[i][j];
            if (EPI >= 1) v += bias[col];
            if (EPI == 2) v = gelu_new(v);
            if (EPI == 3) v += res[base + col];
            C[base + col] = v;
        }
    }
}

// ---------------- top-k (k=16) per row over 32768 scores ---------------------
// one block (256 thr) per token row
__global__ void topk_kernel() {
    int row = blockIdx.x;
    int t = threadIdx.x;
    const float* s = g_scores + (size_t)row * MDB;

    float lv[KSEL];
    int   li[KSEL];
#pragma unroll
    for (int i = 0; i < KSEL; i++) { lv[i] = -FLT_MAX; li[i] = 0x7fffffff; }

    for (int j = t; j < MDB; j += 256) {
        float v = s[j];
        if (v > lv[KSEL - 1]) {
            int p = KSEL - 1;
            while (p > 0 && lv[p - 1] < v) {
                lv[p] = lv[p - 1]; li[p] = li[p - 1]; p--;
            }
            lv[p] = v; li[p] = j;
        }
    }

    __shared__ float cv[256];
    __shared__ int   ci[256];
    __shared__ int   ctid[256];
    int p = 0;
    for (int r = 0; r < KSEL; r++) {
        cv[t] = (p < KSEL) ? lv[p] : -FLT_MAX;
        ci[t] = (p < KSEL) ? li[p] : 0x7fffffff;
        ctid[t] = t;
        __syncthreads();
        for (int off = 128; off > 0; off >>= 1) {
            if (t < off) {
                float a = cv[t], b = cv[t + off];
                if (b > a || (b == a && ci[t + off] < ci[t])) {
                    cv[t] = b; ci[t] = ci[t + off]; ctid[t] = ctid[t + off];
                }
            }
            __syncthreads();
        }
        int wt = ctid[0];
        if (t == 0) g_idx[row * KSEL + r] = ci[0];
        __syncthreads();
        if (t == wt) p++;
    }
}

// ---------------- gather + per-token softmax attention ------------------------
// one block (128 thr) per token
__global__ void attn_kernel(const float* __restrict__ dbk,
                            const float* __restrict__ dbv) {
    int tok = blockIdx.x;
    int t = threadIdx.x;
    int w = t >> 5, l = t & 31;

    __shared__ float qs[DMODEL];
    __shared__ int   idxs[KSEL];
    __shared__ float sc[NHEAD * KSEL];
    __shared__ float wts[NHEAD * KSEL];

    if (t < KSEL) idxs[t] = g_idx[tok * KSEL + t];
    for (int i = t; i < DMODEL; i += 128) qs[i] = g_q[(size_t)tok * DMODEL + i];
    __syncthreads();

    // 12 heads x 16 memories = 192 dot products of length 64; warp w handles 48
    for (int pp = w * 48; pp < (w + 1) * 48; pp++) {
        int h = pp >> 4, k = pp & 15;
        const float* kr = dbk + (size_t)idxs[k] * DMODEL + h * HDIM;
        float2 kv = ((const float2*)kr)[l];
        float2 qv = ((const float2*)(qs + h * HDIM))[l];
        float d = kv.x * qv.x + kv.y * qv.y;
#pragma unroll
        for (int o = 16; o; o >>= 1) d += __shfl_xor_sync(0xffffffffu, d, o);
        if (l == 0) sc[pp] = d * 0.125f;   // 1/sqrt(64)
    }
    __syncthreads();

    if (t < NHEAD) {
        float mx = -FLT_MAX;
#pragma unroll
        for (int k = 0; k < KSEL; k++) mx = fmaxf(mx, sc[t * KSEL + k]);
        float sum = 0.f;
#pragma unroll
        for (int k = 0; k < KSEL; k++) {
            float e = expf(sc[t * KSEL + k] - mx);
            wts[t * KSEL + k] = e;
            sum += e;
        }
        float inv = 1.0f / sum;
#pragma unroll
        for (int k = 0; k < KSEL; k++) wts[t * KSEL + k] *= inv;
    }
    __syncthreads();

    float acc[6] = {0.f, 0.f, 0.f, 0.f, 0.f, 0.f};
    int hh[6];
#pragma unroll
    for (int j = 0; j < 6; j++) hh[j] = (t + j * 128) >> 6;
    for (int k = 0; k < KSEL; k++) {
        const float* vr = dbv + (size_t)idxs[k] * DMODEL;
#pragma unroll
        for (int j = 0; j < 6; j++) {
            acc[j] += wts[hh[j] * KSEL + k] * vr[t + j * 128];
        }
    }
    float* orow = g_attn + (size_t)tok * DMODEL;
#pragma unroll
    for (int j = 0; j < 6; j++) orow[t + j * 128] = acc[j];
}

// ---------------- launch ------------------------------------------------------
extern "C" void kernel_launch(void* const* d_in, const int* in_sizes, int n_in,
                              void* d_out, int out_size) {
    const float* prev     = (const float*)d_in[0];
    const float* db_keys  = (const float*)d_in[1];
    const float* db_vals  = (const float*)d_in[2];
    const float* ln1_g    = (const float*)d_in[3];
    const float* ln1_b    = (const float*)d_in[4];
    const float* c_attn_w = (const float*)d_in[5];
    const float* c_attn_b = (const float*)d_in[6];
    const float* c_proj_w = (const float*)d_in[7];
    const float* c_proj_b = (const float*)d_in[8];
    const float* ln2_g    = (const float*)d_in[9];
    const float* ln2_b    = (const float*)d_in[10];
    const float* fc_w     = (const float*)d_in[11];
    const float* fc_b     = (const float*)d_in[12];
    const float* proj_w   = (const float*)d_in[13];
    const float* proj_b   = (const float*)d_in[14];
    float* out = (float*)d_out;

    float *p_h1, *p_q, *p_scores, *p_attn, *p_res2, *p_h2, *p_ff;
    cudaGetSymbolAddress((void**)&p_h1, g_h1);
    cudaGetSymbolAddress((void**)&p_q, g_q);
    cudaGetSymbolAddress((void**)&p_scores, g_scores);
    cudaGetSymbolAddress((void**)&p_attn, g_attn);
    cudaGetSymbolAddress((void**)&p_res2, g_res2);
    cudaGetSymbolAddress((void**)&p_h2, g_h2);
    cudaGetSymbolAddress((void**)&p_ff, g_ff);

    // 1. LN1
    ln_kernel<<<NTOK, 256>>>(prev, ln1_g, ln1_b, p_h1);
    // 2. q projection (only the q third of c_attn is live)
    gemm_kernel<false, 1><<<dim3(DMODEL / 64, NTOK / 64), 256>>>(
        p_h1, c_attn_w, c_attn_b, nullptr, p_q, DMODEL, 3 * DMODEL, DMODEL);
    // 3. KNN scores: q @ db_keys^T
    gemm_kernel<true, 0><<<dim3(MDB / 64, NTOK / 64), 256>>>(
        p_q, db_keys, nullptr, nullptr, p_scores, DMODEL, DMODEL, MDB);
    // 4. top-16 per token
    topk_kernel<<<NTOK, 256>>>();
    // 5. gather + per-token memory attention
    attn_kernel<<<NTOK, 128>>>(db_keys, db_vals);
    // 6. c_proj + residual
    gemm_kernel<false, 3><<<dim3(DMODEL / 64, NTOK / 64), 256>>>(
        p_attn, c_proj_w, c_proj_b, prev, p_res2, DMODEL, DMODEL, DMODEL);
    // 7. LN2
    ln_kernel<<<NTOK, 256>>>(p_res2, ln2_g, ln2_b, p_h2);
    // 8. MLP fc + gelu
    gemm_kernel<false, 2><<<dim3(DFF / 64, NTOK / 64), 256>>>(
        p_h2, fc_w, fc_b, nullptr, p_ff, DMODEL, DFF, DFF);
    // 9. MLP proj + bias + residual2 -> out
    gemm_kernel<false, 3><<<dim3(DMODEL / 64, NTOK / 64), 256>>>(
        p_ff, proj_w, proj_b, p_res2, out, DFF, DMODEL, DMODEL);
}